// round 1
// baseline (speedup 1.0000x reference)
#include <cuda_runtime.h>

// Problem constants
#define NN 16
#define CC 128
#define SS 16384
#define KK 64

#define TC 64            // s-positions per chunk
#define SBLOCKS 18       // s-blocks per image (18*16 = 288 blocks ~ 2/SM on 148 SMs)
#define NCHUNKS (SS/TC)  // 256 chunks per image

// ---- device scratch (no allocations allowed) ----
__device__ float g_vlad[NN*KK*CC];   // raw sum_s soft*xnorm
__device__ float g_asum[NN*KK];      // sum_s soft
__device__ float g_gssq[NN];         // global ssq after intra-norm

// ---- shared memory layout (in floats) ----
#define XT_STRIDE 132                 // 128 + pad, multiple of 4 for 16B loads
#define WT_STRIDE 68                  // 64 + pad
#define SF_STRIDE 68
#define OFF_XT  0
#define OFF_WT  (OFF_XT + TC*XT_STRIDE)        // 8448
#define OFF_SF  (OFF_WT + CC*WT_STRIDE)        // 17152
#define OFF_B   (OFF_SF + TC*SF_STRIDE)        // 21504
#define OFF_INV (OFF_B + 64)                   // 21568
#define OFF_RED (OFF_INV + 64)                 // 21632
#define SMEM_FLOATS (OFF_RED + 256)            // 21888 floats = 87552 B

__global__ void __launch_bounds__(256, 2)
netvlad_main(const float* __restrict__ x,
             const float* __restrict__ fc_w,
             const float* __restrict__ fc_b)
{
    extern __shared__ float smem[];
    const int tid = threadIdx.x;
    const int n   = blockIdx.y;
    const int sb  = blockIdx.x;

    float* XT  = smem + OFF_XT;
    float* WT  = smem + OFF_WT;
    float* SF  = smem + OFF_SF;
    float* Bb  = smem + OFF_B;
    float* INV = smem + OFF_INV;
    float* RED = smem + OFF_RED;

    // load W transposed: WT[c][k] = fc_w[k][c]; bias
    for (int i = tid; i < KK*CC; i += 256) {
        int k = i >> 7, c = i & 127;
        WT[c*WT_STRIDE + k] = fc_w[i];
    }
    if (tid < 64) Bb[tid] = fc_b[tid];

    // ---- thread mappings ----
    // Phase A (logits): 8 k per thread (packed as 4 pairs), 2 t per thread
    const int k0A = (tid & 7) * 8;
    const int t0A = (tid >> 3) * 2;
    // softmax: 4 threads per t, 16 k each
    const int tqS = tid & 3;
    const int tS  = tid >> 2;
    // Phase B (vlad): 4 k x 8 c per thread (c packed as 4 pairs)
    const int k0B = (tid >> 4) * 4;
    const int c0B = (tid & 15) * 8;
    // loader: fixed t per thread, c-residue class
    const int tL = tid & 63;

    const unsigned shm = (unsigned)__cvta_generic_to_shared(smem);
    const unsigned wt_sh  = shm + (unsigned)(OFF_WT + k0A) * 4u;
    const unsigned sf_st0 = shm + (unsigned)(OFF_SF + t0A*SF_STRIDE + k0A) * 4u;
    const unsigned sf_st1 = sf_st0 + (unsigned)(SF_STRIDE * 4);
    const unsigned xb_sh  = shm + (unsigned)(OFF_XT + c0B) * 4u;

    // persistent accumulators
    unsigned long long accV[4][4];   // [k][c-pair], packed f32x2
    #pragma unroll
    for (int i = 0; i < 4; i++)
        #pragma unroll
        for (int j = 0; j < 4; j++) accV[i][j] = 0ULL;
    float asum_loc[16];
    #pragma unroll
    for (int i = 0; i < 16; i++) asum_loc[i] = 0.f;

    const float* xn = x + (size_t)n * CC * SS;

    __syncthreads();

    // bias packs for phase A init
    unsigned long long bp[4];
    #pragma unroll
    for (int kp = 0; kp < 4; kp++) {
        float b0 = Bb[k0A + 2*kp], b1 = Bb[k0A + 2*kp + 1];
        asm("mov.b64 %0,{%1,%2};" : "=l"(bp[kp]) : "f"(b0), "f"(b1));
    }

    for (int cs = sb; cs < NCHUNKS; cs += SBLOCKS) {
        const int s0 = cs * TC;

        // ---- load x chunk (coalesced) + ssq partials in registers ----
        float ssq = 0.f;
        #pragma unroll
        for (int it = 0; it < 32; it++) {
            int i = tid + 256*it;
            int c = i >> 6;                 // fixed residue class per thread
            float v = xn[(size_t)c*SS + (s0 + tL)];
            XT[tL*XT_STRIDE + c] = v;
            ssq += v*v;
        }
        RED[(tid >> 6)*64 + tL] = ssq;
        __syncthreads();
        if (tid < 64) {
            float s = RED[tid] + RED[64+tid] + RED[128+tid] + RED[192+tid];
            INV[tid] = 1.f / fmaxf(sqrtf(s), 1e-12f);
        }
        __syncthreads();
        // ---- normalize in place (linear, conflict-free) ----
        #pragma unroll
        for (int it = 0; it < (TC*XT_STRIDE)/256; it++) {
            int idx = tid + 256*it;
            XT[idx] *= INV[idx / XT_STRIDE];
        }
        __syncthreads();

        // ---- Phase A: logits[64][TC] = W @ Xnorm + b  (packed f32x2 along k) ----
        {
            unsigned long long a0[4], a1[4];
            #pragma unroll
            for (int kp = 0; kp < 4; kp++) { a0[kp] = bp[kp]; a1[kp] = bp[kp]; }
            const float* xr0 = XT + t0A*XT_STRIDE;
            const float* xr1 = xr0 + XT_STRIDE;
            #pragma unroll 4
            for (int c = 0; c < CC; c++) {
                float x0 = xr0[c], x1 = xr1[c];
                unsigned long long x0p, x1p, w01, w23, w45, w67;
                asm("mov.b64 %0,{%1,%1};" : "=l"(x0p) : "f"(x0));
                asm("mov.b64 %0,{%1,%1};" : "=l"(x1p) : "f"(x1));
                unsigned wa = wt_sh + (unsigned)(c * (WT_STRIDE*4));
                asm volatile("ld.shared.v2.u64 {%0,%1},[%2];" : "=l"(w01), "=l"(w23) : "r"(wa));
                asm volatile("ld.shared.v2.u64 {%0,%1},[%2];" : "=l"(w45), "=l"(w67) : "r"(wa+16));
                asm("fma.rn.f32x2 %0,%1,%2,%0;" : "+l"(a0[0]) : "l"(x0p), "l"(w01));
                asm("fma.rn.f32x2 %0,%1,%2,%0;" : "+l"(a0[1]) : "l"(x0p), "l"(w23));
                asm("fma.rn.f32x2 %0,%1,%2,%0;" : "+l"(a0[2]) : "l"(x0p), "l"(w45));
                asm("fma.rn.f32x2 %0,%1,%2,%0;" : "+l"(a0[3]) : "l"(x0p), "l"(w67));
                asm("fma.rn.f32x2 %0,%1,%2,%0;" : "+l"(a1[0]) : "l"(x1p), "l"(w01));
                asm("fma.rn.f32x2 %0,%1,%2,%0;" : "+l"(a1[1]) : "l"(x1p), "l"(w23));
                asm("fma.rn.f32x2 %0,%1,%2,%0;" : "+l"(a1[2]) : "l"(x1p), "l"(w45));
                asm("fma.rn.f32x2 %0,%1,%2,%0;" : "+l"(a1[3]) : "l"(x1p), "l"(w67));
            }
            asm volatile("st.shared.v2.u64 [%0],{%1,%2};" :: "r"(sf_st0),    "l"(a0[0]), "l"(a0[1]));
            asm volatile("st.shared.v2.u64 [%0],{%1,%2};" :: "r"(sf_st0+16), "l"(a0[2]), "l"(a0[3]));
            asm volatile("st.shared.v2.u64 [%0],{%1,%2};" :: "r"(sf_st1),    "l"(a1[0]), "l"(a1[1]));
            asm volatile("st.shared.v2.u64 [%0],{%1,%2};" :: "r"(sf_st1+16), "l"(a1[2]), "l"(a1[3]));
        }
        __syncthreads();

        // ---- softmax over k (64), 4 threads per t ----
        {
            float v[16];
            float* row = SF + tS*SF_STRIDE + tqS*16;
            #pragma unroll
            for (int j = 0; j < 16; j++) v[j] = row[j];
            float mx = v[0];
            #pragma unroll
            for (int j = 1; j < 16; j++) mx = fmaxf(mx, v[j]);
            mx = fmaxf(mx, __shfl_xor_sync(0xffffffffu, mx, 1));
            mx = fmaxf(mx, __shfl_xor_sync(0xffffffffu, mx, 2));
            float sum = 0.f;
            #pragma unroll
            for (int j = 0; j < 16; j++) { v[j] = __expf(v[j] - mx); sum += v[j]; }
            sum += __shfl_xor_sync(0xffffffffu, sum, 1);
            sum += __shfl_xor_sync(0xffffffffu, sum, 2);
            float rs = 1.f / sum;
            #pragma unroll
            for (int j = 0; j < 16; j++) {
                float s = v[j] * rs;
                row[j] = s;
                asum_loc[j] += s;
            }
        }
        __syncthreads();

        // ---- Phase B: vlad[64][128] += soft @ Xnorm^T  (packed f32x2 along c) ----
        #pragma unroll 2
        for (int t = 0; t < TC; t++) {
            const float4 sv = *(const float4*)(SF + t*SF_STRIDE + k0B);
            unsigned xa = xb_sh + (unsigned)(t * (XT_STRIDE*4));
            unsigned long long xp0, xp1, xp2, xp3;
            asm volatile("ld.shared.v2.u64 {%0,%1},[%2];" : "=l"(xp0), "=l"(xp1) : "r"(xa));
            asm volatile("ld.shared.v2.u64 {%0,%1},[%2];" : "=l"(xp2), "=l"(xp3) : "r"(xa+16));
            unsigned long long sp[4];
            asm("mov.b64 %0,{%1,%1};" : "=l"(sp[0]) : "f"(sv.x));
            asm("mov.b64 %0,{%1,%1};" : "=l"(sp[1]) : "f"(sv.y));
            asm("mov.b64 %0,{%1,%1};" : "=l"(sp[2]) : "f"(sv.z));
            asm("mov.b64 %0,{%1,%1};" : "=l"(sp[3]) : "f"(sv.w));
            #pragma unroll
            for (int i = 0; i < 4; i++) {
                asm("fma.rn.f32x2 %0,%1,%2,%0;" : "+l"(accV[i][0]) : "l"(sp[i]), "l"(xp0));
                asm("fma.rn.f32x2 %0,%1,%2,%0;" : "+l"(accV[i][1]) : "l"(sp[i]), "l"(xp1));
                asm("fma.rn.f32x2 %0,%1,%2,%0;" : "+l"(accV[i][2]) : "l"(sp[i]), "l"(xp2));
                asm("fma.rn.f32x2 %0,%1,%2,%0;" : "+l"(accV[i][3]) : "l"(sp[i]), "l"(xp3));
            }
        }
        __syncthreads();   // before next chunk overwrites XT/SF
    }

    // ---- epilogue: vlad partials -> global ----
    #pragma unroll
    for (int i = 0; i < 4; i++) {
        size_t base = ((size_t)n*KK + (k0B + i))*CC + c0B;
        #pragma unroll
        for (int j = 0; j < 4; j++) {
            float lo, hi;
            asm("mov.b64 {%0,%1},%2;" : "=f"(lo), "=f"(hi) : "l"(accV[i][j]));
            atomicAdd(&g_vlad[base + 2*j],     lo);
            atomicAdd(&g_vlad[base + 2*j + 1], hi);
        }
    }
    // ---- a_sum reduction via SF staging ----
    #pragma unroll
    for (int j = 0; j < 16; j++) SF[tid*16 + j] = asum_loc[j];
    __syncthreads();
    if (tid < 64) {
        int k = tid, tq = k >> 4, kj = k & 15;
        float s = 0.f;
        for (int tt = 0; tt < 64; tt++) s += SF[(tt*4 + tq)*16 + kj];
        atomicAdd(&g_asum[n*KK + k], s);
    }
}

__global__ void zero_kernel()
{
    int i = blockIdx.x*256 + threadIdx.x;
    if (i < NN*KK*CC) g_vlad[i] = 0.f;
    if (i < NN*KK)    g_asum[i] = 0.f;
    if (i < NN)       g_gssq[i] = 0.f;
}

__global__ void finalize1(const float* __restrict__ centroids, float* __restrict__ out)
{
    __shared__ float red[4];
    const int n = blockIdx.y, k = blockIdx.x;
    const int c = threadIdx.x;   // 128 threads
    float a = g_asum[n*KK + k];
    float v = g_vlad[((size_t)n*KK + k)*CC + c] - a * centroids[k*CC + c];
    float ss = v*v;
    #pragma unroll
    for (int o = 16; o; o >>= 1) ss += __shfl_xor_sync(0xffffffffu, ss, o);
    if ((c & 31) == 0) red[c >> 5] = ss;
    __syncthreads();
    float tot = red[0] + red[1] + red[2] + red[3];
    float inv = 1.f / fmaxf(sqrtf(tot), 1e-12f);
    out[((size_t)n*KK + k)*CC + c] = v * inv;
    if (c == 0) atomicAdd(&g_gssq[n], tot * inv * inv);
}

__global__ void finalize2(float* __restrict__ out)
{
    int i = blockIdx.x*256 + threadIdx.x;   // 131072 total
    int n = i >> 13;
    out[i] *= 1.f / fmaxf(sqrtf(g_gssq[n]), 1e-12f);
}

extern "C" void kernel_launch(void* const* d_in, const int* in_sizes, int n_in,
                              void* d_out, int out_size)
{
    const float* x         = (const float*)d_in[0];
    const float* fc_w      = (const float*)d_in[1];
    const float* fc_b      = (const float*)d_in[2];
    const float* centroids = (const float*)d_in[3];
    float* out = (float*)d_out;

    cudaFuncSetAttribute((const void*)netvlad_main,
                         cudaFuncAttributeMaxDynamicSharedMemorySize,
                         SMEM_FLOATS * 4);

    zero_kernel<<<(NN*KK*CC + 255)/256, 256>>>();
    dim3 grid(SBLOCKS, NN);
    netvlad_main<<<grid, 256, SMEM_FLOATS * 4>>>(x, fc_w, fc_b);
    finalize1<<<dim3(KK, NN), 128>>>(centroids, out);
    finalize2<<<(NN*KK*CC + 255)/256, 256>>>(out);
}

// round 16
// speedup vs baseline: 1.4751x; 1.4751x over previous
#include <cuda_runtime.h>

// Problem constants
#define NN 16
#define CC 128
#define SS 16384
#define KK 64

#define TC 64            // s-positions per chunk
#define SBLOCKS 18       // 18*16 = 288 CTAs ~ 2/SM on 148 SMs (single wave at occ 2)
#define NCHUNKS (SS/TC)  // 256 chunks per image

// ---- device scratch ----
__device__ float g_vlad[NN*KK*CC];
__device__ float g_asum[NN*KK];
__device__ float g_gssq[NN];

// ---- shared layout (floats) ----
// XT double buffer: raw x, [t][c] with per-row XOR swizzle, stride 128
#define XT_STRIDE 128
#define OFF_XT0 0
#define OFF_XT1 (TC*XT_STRIDE)                  // 8192
#define OFF_WT  (2*TC*XT_STRIDE)                // 16384, W^T [c][k], stride 64
#define OFF_SF  (OFF_WT + CC*KK)                // 24576, soft*inv [t][k], stride 64
#define SMEM_FLOATS (OFF_SF + TC*KK)            // 28672 floats = 114688 B

#define FMA2(acc, a, b) asm("fma.rn.f32x2 %0,%1,%2,%0;" : "+l"(acc) : "l"(a), "l"(b))
#define SPLAT(p, x)     asm("mov.b64 %0,{%1,%1};" : "=l"(p) : "f"(x))
#define UNPK(lo, hi, p) asm("mov.b64 {%0,%1},%2;" : "=f"(lo), "=f"(hi) : "l"(p))

__device__ __forceinline__ void prefetch_chunk(const float* __restrict__ xn, int s0,
                                               unsigned xt_byte, int tid)
{
    const int tL   = tid & 63;
    const int cb   = tid >> 6;
    const int swz  = (tL & 31) << 2;
    const unsigned dstrow = xt_byte + (unsigned)(tL * (XT_STRIDE*4));
    const float* src = xn + s0 + tL;
    #pragma unroll
    for (int it = 0; it < 32; it++) {
        int c = cb + 4*it;
        unsigned d = dstrow + (unsigned)((c ^ swz) << 2);
        const float* s = src + (size_t)c * SS;
        asm volatile("cp.async.ca.shared.global [%0],[%1],4;" :: "r"(d), "l"(s));
    }
}

__global__ void __launch_bounds__(256, 2)
netvlad_main(const float* __restrict__ x,
             const float* __restrict__ fc_w,
             const float* __restrict__ fc_b)
{
    extern __shared__ float smem[];
    const int tid = threadIdx.x;
    const int n   = blockIdx.y;
    const int sb  = blockIdx.x;

    float* SF = smem + OFF_SF;
    const unsigned shmu = (unsigned)__cvta_generic_to_shared(smem);
    const unsigned xtb0 = shmu + OFF_XT0*4u;
    const unsigned xtb1 = shmu + OFF_XT1*4u;

    // load W transposed: WT[c*64 + k] = fc_w[k*128 + c]
    for (int i = tid; i < KK*CC; i += 256) {
        int k = i & 63, c = i >> 6;
        smem[OFF_WT + c*64 + k] = fc_w[k*CC + c];
    }

    // ---- thread mappings ----
    const int g   = tid & 7;          // Phase A k-group: k in {4g..4g+3, 32+4g..32+4g+3}
    const int t0  = (tid >> 3) * 2;   // Phase A rows t0, t0+1
    const int t1  = t0 + 1;
    const int swz0 = (t0 & 31) << 2;
    const int swz1 = (t1 & 31) << 2;
    const int kB  = (tid >> 4) * 4;   // Phase B: 4 k
    const int mm  = tid & 15;         // Phase B: c in {2mm,2mm+1} + 32q

    // bias registers for this thread's 8 k
    float bj[8];
    #pragma unroll
    for (int j = 0; j < 4; j++) { bj[j] = fc_b[4*g + j]; bj[4+j] = fc_b[32 + 4*g + j]; }

    // persistent accumulators
    unsigned long long accV[4][4];
    #pragma unroll
    for (int i = 0; i < 4; i++)
        #pragma unroll
        for (int q = 0; q < 4; q++) accV[i][q] = 0ULL;
    float asum_loc[8];
    #pragma unroll
    for (int j = 0; j < 8; j++) asum_loc[j] = 0.f;

    const float* xn = x + (size_t)n * CC * SS;
    const unsigned wbase = shmu + OFF_WT*4u + (unsigned)(g*16);
    const int idxq[4] = { 2*mm, 32 + 2*mm, 64 + 2*mm, 96 + 2*mm };

    // prologue prefetch
    prefetch_chunk(xn, sb*TC, xtb0, tid);
    asm volatile("cp.async.commit_group;" ::: "memory");

    int mI = 0;
    for (int cs = sb; cs < NCHUNKS; cs += SBLOCKS, mI++) {
        const unsigned xtb = (mI & 1) ? xtb1 : xtb0;
        const unsigned xtn = (mI & 1) ? xtb0 : xtb1;
        const float* XTc = smem + ((mI & 1) ? OFF_XT1 : OFF_XT0);

        asm volatile("cp.async.wait_group 0;" ::: "memory");
        __syncthreads();                         // chunk cs landed; prev Phase B done

        int csn = cs + SBLOCKS;
        if (csn < NCHUNKS) {
            prefetch_chunk(xn, csn*TC, xtn, tid);
            asm volatile("cp.async.commit_group;" ::: "memory");
        }

        const float* row0 = XTc + t0*XT_STRIDE;
        const float* row1 = row0 + XT_STRIDE;

        // ---- per-row ssq (each thread sums its 16-c slice, shfl over 8-group) ----
        float ssq0 = 0.f, ssq1 = 0.f;
        #pragma unroll
        for (int u = 0; u < 4; u++) {
            float4 v0 = *(const float4*)(row0 + ((16*g + 4*u) ^ swz0));
            float4 v1 = *(const float4*)(row1 + ((16*g + 4*u) ^ swz1));
            ssq0 += v0.x*v0.x + v0.y*v0.y + v0.z*v0.z + v0.w*v0.w;
            ssq1 += v1.x*v1.x + v1.y*v1.y + v1.z*v1.z + v1.w*v1.w;
        }
        ssq0 += __shfl_xor_sync(0xffffffffu, ssq0, 1);
        ssq0 += __shfl_xor_sync(0xffffffffu, ssq0, 2);
        ssq0 += __shfl_xor_sync(0xffffffffu, ssq0, 4);
        ssq1 += __shfl_xor_sync(0xffffffffu, ssq1, 1);
        ssq1 += __shfl_xor_sync(0xffffffffu, ssq1, 2);
        ssq1 += __shfl_xor_sync(0xffffffffu, ssq1, 4);
        const float inv0 = __fdividef(1.f, fmaxf(sqrtf(ssq0), 1e-12f));
        const float inv1 = __fdividef(1.f, fmaxf(sqrtf(ssq1), 1e-12f));

        // ---- Phase A: raw logits, packed f32x2 along k ----
        unsigned long long a0[4] = {0,0,0,0}, a1[4] = {0,0,0,0};
        #pragma unroll 1
        for (int i = 0; i < 32; i++) {
            const float4 xv0 = *(const float4*)(row0 + ((4*i) ^ swz0));
            const float4 xv1 = *(const float4*)(row1 + ((4*i) ^ swz1));
            #pragma unroll
            for (int u = 0; u < 4; u++) {
                const float x0 = (&xv0.x)[u];
                const float x1 = (&xv1.x)[u];
                unsigned long long x0p, x1p, wA, wB, wC, wD;
                SPLAT(x0p, x0);
                SPLAT(x1p, x1);
                unsigned wa = wbase + (unsigned)((4*i + u) << 8);
                asm volatile("ld.shared.v2.u64 {%0,%1},[%2];" : "=l"(wA), "=l"(wB) : "r"(wa));
                asm volatile("ld.shared.v2.u64 {%0,%1},[%2];" : "=l"(wC), "=l"(wD) : "r"(wa + 128));
                FMA2(a0[0], x0p, wA); FMA2(a0[1], x0p, wB);
                FMA2(a0[2], x0p, wC); FMA2(a0[3], x0p, wD);
                FMA2(a1[0], x1p, wA); FMA2(a1[1], x1p, wB);
                FMA2(a1[2], x1p, wC); FMA2(a1[3], x1p, wD);
            }
        }

        // ---- fused softmax over k (shfl across the 8-lane k-group) ----
        {
            float l0[8], l1[8];
            UNPK(l0[0], l0[1], a0[0]); UNPK(l0[2], l0[3], a0[1]);
            UNPK(l0[4], l0[5], a0[2]); UNPK(l0[6], l0[7], a0[3]);
            UNPK(l1[0], l1[1], a1[0]); UNPK(l1[2], l1[3], a1[1]);
            UNPK(l1[4], l1[5], a1[2]); UNPK(l1[6], l1[7], a1[3]);
            #pragma unroll
            for (int j = 0; j < 8; j++) {
                l0[j] = fmaf(l0[j], inv0, bj[j]);
                l1[j] = fmaf(l1[j], inv1, bj[j]);
            }
            float m0 = l0[0], m1 = l1[0];
            #pragma unroll
            for (int j = 1; j < 8; j++) { m0 = fmaxf(m0, l0[j]); m1 = fmaxf(m1, l1[j]); }
            m0 = fmaxf(m0, __shfl_xor_sync(0xffffffffu, m0, 1));
            m0 = fmaxf(m0, __shfl_xor_sync(0xffffffffu, m0, 2));
            m0 = fmaxf(m0, __shfl_xor_sync(0xffffffffu, m0, 4));
            m1 = fmaxf(m1, __shfl_xor_sync(0xffffffffu, m1, 1));
            m1 = fmaxf(m1, __shfl_xor_sync(0xffffffffu, m1, 2));
            m1 = fmaxf(m1, __shfl_xor_sync(0xffffffffu, m1, 4));
            float s0 = 0.f, s1 = 0.f;
            #pragma unroll
            for (int j = 0; j < 8; j++) {
                l0[j] = __expf(l0[j] - m0); s0 += l0[j];
                l1[j] = __expf(l1[j] - m1); s1 += l1[j];
            }
            s0 += __shfl_xor_sync(0xffffffffu, s0, 1);
            s0 += __shfl_xor_sync(0xffffffffu, s0, 2);
            s0 += __shfl_xor_sync(0xffffffffu, s0, 4);
            s1 += __shfl_xor_sync(0xffffffffu, s1, 1);
            s1 += __shfl_xor_sync(0xffffffffu, s1, 2);
            s1 += __shfl_xor_sync(0xffffffffu, s1, 4);
            const float rs0 = __fdividef(1.f, s0);
            const float rs1 = __fdividef(1.f, s1);
            #pragma unroll
            for (int j = 0; j < 8; j++) {
                float p0 = l0[j] * rs0, p1 = l1[j] * rs1;
                asum_loc[j] += p0 + p1;
                l0[j] = p0 * inv0;            // fold per-position inv into weights
                l1[j] = p1 * inv1;
            }
            *(float4*)(SF + t0*64 + 4*g)      = make_float4(l0[0], l0[1], l0[2], l0[3]);
            *(float4*)(SF + t0*64 + 32 + 4*g) = make_float4(l0[4], l0[5], l0[6], l0[7]);
            *(float4*)(SF + t1*64 + 4*g)      = make_float4(l1[0], l1[1], l1[2], l1[3]);
            *(float4*)(SF + t1*64 + 32 + 4*g) = make_float4(l1[4], l1[5], l1[6], l1[7]);
        }
        __syncthreads();                       // SF ready

        // ---- Phase B: vlad += soft_hat @ x_raw^T (packed f32x2 along c) ----
        #pragma unroll 2
        for (int t = 0; t < TC; t++) {
            const float4 sv = *(const float4*)(SF + t*64 + kB);
            const unsigned rb = xtb + (unsigned)(t * (XT_STRIDE*4));
            const int swz = (t & 31) << 2;
            unsigned long long xp0, xp1, xp2, xp3;
            asm volatile("ld.shared.b64 %0,[%1];" : "=l"(xp0) : "r"(rb + (unsigned)((idxq[0] ^ swz) << 2)));
            asm volatile("ld.shared.b64 %0,[%1];" : "=l"(xp1) : "r"(rb + (unsigned)((idxq[1] ^ swz) << 2)));
            asm volatile("ld.shared.b64 %0,[%1];" : "=l"(xp2) : "r"(rb + (unsigned)((idxq[2] ^ swz) << 2)));
            asm volatile("ld.shared.b64 %0,[%1];" : "=l"(xp3) : "r"(rb + (unsigned)((idxq[3] ^ swz) << 2)));
            unsigned long long sp0, sp1, sp2, sp3;
            SPLAT(sp0, sv.x); SPLAT(sp1, sv.y); SPLAT(sp2, sv.z); SPLAT(sp3, sv.w);
            FMA2(accV[0][0], sp0, xp0); FMA2(accV[0][1], sp0, xp1);
            FMA2(accV[0][2], sp0, xp2); FMA2(accV[0][3], sp0, xp3);
            FMA2(accV[1][0], sp1, xp0); FMA2(accV[1][1], sp1, xp1);
            FMA2(accV[1][2], sp1, xp2); FMA2(accV[1][3], sp1, xp3);
            FMA2(accV[2][0], sp2, xp0); FMA2(accV[2][1], sp2, xp1);
            FMA2(accV[2][2], sp2, xp2); FMA2(accV[2][3], sp2, xp3);
            FMA2(accV[3][0], sp3, xp0); FMA2(accV[3][1], sp3, xp1);
            FMA2(accV[3][2], sp3, xp2); FMA2(accV[3][3], sp3, xp3);
        }
    }

    // ---- epilogue: vlad partials ----
    #pragma unroll
    for (int i = 0; i < 4; i++) {
        #pragma unroll
        for (int q = 0; q < 4; q++) {
            float lo, hi;
            UNPK(lo, hi, accV[i][q]);
            size_t base = ((size_t)n*KK + (kB + i))*CC + (32*q + 2*mm);
            atomicAdd(&g_vlad[base],     lo);
            atomicAdd(&g_vlad[base + 1], hi);
        }
    }
    // ---- a_sum reduction (stage in SF) ----
    __syncthreads();
    #pragma unroll
    for (int j = 0; j < 8; j++) SF[tid*8 + j] = asum_loc[j];
    __syncthreads();
    if (tid < 64) {
        int k = tid;
        int gg = (k < 32) ? (k >> 2) : ((k - 32) >> 2);
        int jj = (k < 32) ? (k & 3)  : (4 + (k & 3));
        float s = 0.f;
        for (int q = 0; q < 32; q++) s += SF[(q*8 + gg)*8 + jj];
        atomicAdd(&g_asum[n*KK + k], s);
    }
}

__global__ void zero_kernel()
{
    int i = blockIdx.x*256 + threadIdx.x;
    if (i < NN*KK*CC) g_vlad[i] = 0.f;
    if (i < NN*KK)    g_asum[i] = 0.f;
    if (i < NN)       g_gssq[i] = 0.f;
}

__global__ void finalize1(const float* __restrict__ centroids, float* __restrict__ out)
{
    __shared__ float red[4];
    const int n = blockIdx.y, k = blockIdx.x;
    const int c = threadIdx.x;   // 128 threads
    float a = g_asum[n*KK + k];
    float v = g_vlad[((size_t)n*KK + k)*CC + c] - a * centroids[k*CC + c];
    float ss = v*v;
    #pragma unroll
    for (int o = 16; o; o >>= 1) ss += __shfl_xor_sync(0xffffffffu, ss, o);
    if ((c & 31) == 0) red[c >> 5] = ss;
    __syncthreads();
    float tot = red[0] + red[1] + red[2] + red[3];
    float inv = 1.f / fmaxf(sqrtf(tot), 1e-12f);
    out[((size_t)n*KK + k)*CC + c] = v * inv;
    if (c == 0) atomicAdd(&g_gssq[n], tot * inv * inv);
}

__global__ void finalize2(float* __restrict__ out)
{
    int i = blockIdx.x*256 + threadIdx.x;   // 131072 total
    int n = i >> 13;
    out[i] *= 1.f / fmaxf(sqrtf(g_gssq[n]), 1e-12f);
}

extern "C" void kernel_launch(void* const* d_in, const int* in_sizes, int n_in,
                              void* d_out, int out_size)
{
    const float* x         = (const float*)d_in[0];
    const float* fc_w      = (const float*)d_in[1];
    const float* fc_b      = (const float*)d_in[2];
    const float* centroids = (const float*)d_in[3];
    float* out = (float*)d_out;

    cudaFuncSetAttribute((const void*)netvlad_main,
                         cudaFuncAttributeMaxDynamicSharedMemorySize,
                         SMEM_FLOATS * 4);

    zero_kernel<<<(NN*KK*CC + 255)/256, 256>>>();
    dim3 grid(SBLOCKS, NN);
    netvlad_main<<<grid, 256, SMEM_FLOATS * 4>>>(x, fc_w, fc_b);
    finalize1<<<dim3(KK, NN), 128>>>(centroids, out);
    finalize2<<<(NN*KK*CC + 255)/256, 256>>>(out);
}

// round 17
// speedup vs baseline: 1.5355x; 1.0410x over previous
#include <cuda_runtime.h>

// Problem constants
#define NN 16
#define CC 128
#define SS 16384
#define KK 64

#define TC 64            // s-positions per chunk
#define SBLOCKS 18       // 18*16 = 288 CTAs ~ 2/SM on 148 SMs (single wave at occ 2)
#define NCHUNKS (SS/TC)  // 256 chunks per image

#define LOG2E 1.44269504f

// ---- device scratch ----
__device__ float g_vlad[NN*KK*CC];
__device__ float g_asum[NN*KK];
__device__ float g_gssq[NN];

// ---- shared layout (floats) ----
// XT double buffer: raw x, [t][c] with per-row XOR swizzle, stride 128
#define XT_STRIDE 128
#define OFF_XT0 0
#define OFF_XT1 (TC*XT_STRIDE)                  // 8192
#define OFF_WT  (2*TC*XT_STRIDE)                // 16384, W^T [c][k], stride 64
#define OFF_SF  (OFF_WT + CC*KK)                // 24576, soft*inv [t][k], stride 64
#define SMEM_FLOATS (OFF_SF + TC*KK)            // 28672 floats = 114688 B

#define FMA2(acc, a, b) asm("fma.rn.f32x2 %0,%1,%2,%0;" : "+l"(acc) : "l"(a), "l"(b))
#define SPLAT(p, x)     asm("mov.b64 %0,{%1,%1};" : "=l"(p) : "f"(x))
#define UNPK(lo, hi, p) asm("mov.b64 {%0,%1},%2;" : "=f"(lo), "=f"(hi) : "l"(p))

__device__ __forceinline__ void prefetch_chunk(const float* __restrict__ xn, int s0,
                                               unsigned xt_byte, int tid)
{
    const int tL   = tid & 63;
    const int cb   = tid >> 6;
    const int swz  = (tL & 31) << 2;
    const unsigned dstrow = xt_byte + (unsigned)(tL * (XT_STRIDE*4));
    const float* src = xn + s0 + tL;
    #pragma unroll
    for (int it = 0; it < 32; it++) {
        int c = cb + 4*it;
        unsigned d = dstrow + (unsigned)((c ^ swz) << 2);
        const float* s = src + (size_t)c * SS;
        asm volatile("cp.async.ca.shared.global [%0],[%1],4;" :: "r"(d), "l"(s));
    }
}

__global__ void __launch_bounds__(256, 2)
netvlad_main(const float* __restrict__ x,
             const float* __restrict__ fc_w,
             const float* __restrict__ fc_b)
{
    extern __shared__ float smem[];
    const int tid = threadIdx.x;
    const int n   = blockIdx.y;
    const int sb  = blockIdx.x;

    float* SF = smem + OFF_SF;
    const unsigned shmu = (unsigned)__cvta_generic_to_shared(smem);
    const unsigned xtb0 = shmu + OFF_XT0*4u;
    const unsigned xtb1 = shmu + OFF_XT1*4u;

    // load W transposed: WT[c*64 + k] = fc_w[k*128 + c]
    for (int i = tid; i < KK*CC; i += 256) {
        int k = i & 63, c = i >> 6;
        smem[OFF_WT + c*64 + k] = fc_w[k*CC + c];
    }

    // ---- thread mappings ----
    const int g   = tid & 7;          // Phase A k-group: k in {4g..4g+3, 32+4g..32+4g+3}
    const int t0  = (tid >> 3) * 2;   // Phase A rows t0, t0+1
    const int t1  = t0 + 1;
    const int swz0 = (t0 & 31) << 2;
    const int swz1 = (t1 & 31) << 2;
    const int kB  = (tid >> 4) * 4;   // Phase B: 4 k
    const int mm  = tid & 15;         // Phase B: c in {2mm,2mm+1} + 32q

    // bias registers (pre-scaled by log2e for exp2-domain softmax)
    float bjS[8];
    #pragma unroll
    for (int j = 0; j < 4; j++) {
        bjS[j]   = fc_b[4*g + j]      * LOG2E;
        bjS[4+j] = fc_b[32 + 4*g + j] * LOG2E;
    }

    // persistent accumulators
    unsigned long long accV[4][4];
    #pragma unroll
    for (int i = 0; i < 4; i++)
        #pragma unroll
        for (int q = 0; q < 4; q++) accV[i][q] = 0ULL;
    float asum_loc[8];
    #pragma unroll
    for (int j = 0; j < 8; j++) asum_loc[j] = 0.f;

    const float* xn = x + (size_t)n * CC * SS;
    const unsigned wbase = shmu + OFF_WT*4u + (unsigned)(g*16);
    const int idxq[4] = { 2*mm, 32 + 2*mm, 64 + 2*mm, 96 + 2*mm };

    // prologue prefetch
    prefetch_chunk(xn, sb*TC, xtb0, tid);
    asm volatile("cp.async.commit_group;" ::: "memory");

    int mI = 0;
    for (int cs = sb; cs < NCHUNKS; cs += SBLOCKS, mI++) {
        const unsigned xtb = (mI & 1) ? xtb1 : xtb0;
        const unsigned xtn = (mI & 1) ? xtb0 : xtb1;
        const float* XTc = smem + ((mI & 1) ? OFF_XT1 : OFF_XT0);

        asm volatile("cp.async.wait_group 0;" ::: "memory");
        __syncthreads();                         // chunk cs landed; prev Phase B done

        int csn = cs + SBLOCKS;
        if (csn < NCHUNKS) {
            prefetch_chunk(xn, csn*TC, xtn, tid);
            asm volatile("cp.async.commit_group;" ::: "memory");
        }

        const float* row0 = XTc + t0*XT_STRIDE;
        const float* row1 = row0 + XT_STRIDE;

        // ---- per-row ssq (each thread sums its 16-c slice, shfl over 8-group) ----
        float ssq0 = 0.f, ssq1 = 0.f;
        #pragma unroll
        for (int u = 0; u < 4; u++) {
            float4 v0 = *(const float4*)(row0 + ((16*g + 4*u) ^ swz0));
            float4 v1 = *(const float4*)(row1 + ((16*g + 4*u) ^ swz1));
            ssq0 += v0.x*v0.x + v0.y*v0.y + v0.z*v0.z + v0.w*v0.w;
            ssq1 += v1.x*v1.x + v1.y*v1.y + v1.z*v1.z + v1.w*v1.w;
        }
        ssq0 += __shfl_xor_sync(0xffffffffu, ssq0, 1);
        ssq0 += __shfl_xor_sync(0xffffffffu, ssq0, 2);
        ssq0 += __shfl_xor_sync(0xffffffffu, ssq0, 4);
        ssq1 += __shfl_xor_sync(0xffffffffu, ssq1, 1);
        ssq1 += __shfl_xor_sync(0xffffffffu, ssq1, 2);
        ssq1 += __shfl_xor_sync(0xffffffffu, ssq1, 4);
        const float inv0  = __fdividef(1.f, fmaxf(sqrtf(ssq0), 1e-12f));
        const float inv1  = __fdividef(1.f, fmaxf(sqrtf(ssq1), 1e-12f));
        const float invS0 = inv0 * LOG2E;
        const float invS1 = inv1 * LOG2E;

        // ---- Phase A: raw logits, packed f32x2 along k ----
        unsigned long long a0[4] = {0,0,0,0}, a1[4] = {0,0,0,0};
        #pragma unroll 1
        for (int i = 0; i < 32; i++) {
            const float4 xv0 = *(const float4*)(row0 + ((4*i) ^ swz0));
            const float4 xv1 = *(const float4*)(row1 + ((4*i) ^ swz1));
            #pragma unroll
            for (int u = 0; u < 4; u++) {
                const float x0 = (&xv0.x)[u];
                const float x1 = (&xv1.x)[u];
                unsigned long long x0p, x1p, wA, wB, wC, wD;
                SPLAT(x0p, x0);
                SPLAT(x1p, x1);
                unsigned wa = wbase + (unsigned)((4*i + u) << 8);
                asm volatile("ld.shared.v2.u64 {%0,%1},[%2];" : "=l"(wA), "=l"(wB) : "r"(wa));
                asm volatile("ld.shared.v2.u64 {%0,%1},[%2];" : "=l"(wC), "=l"(wD) : "r"(wa + 128));
                FMA2(a0[0], x0p, wA); FMA2(a0[1], x0p, wB);
                FMA2(a0[2], x0p, wC); FMA2(a0[3], x0p, wD);
                FMA2(a1[0], x1p, wA); FMA2(a1[1], x1p, wB);
                FMA2(a1[2], x1p, wC); FMA2(a1[3], x1p, wD);
            }
        }

        // ---- fused softmax over k, exp2-domain, no max-subtraction ----
        // logits bounded (|l| <~ 70): exp2 stays in fp32 range; ratios ≡ reference softmax
        {
            float l0[8], l1[8];
            UNPK(l0[0], l0[1], a0[0]); UNPK(l0[2], l0[3], a0[1]);
            UNPK(l0[4], l0[5], a0[2]); UNPK(l0[6], l0[7], a0[3]);
            UNPK(l1[0], l1[1], a1[0]); UNPK(l1[2], l1[3], a1[1]);
            UNPK(l1[4], l1[5], a1[2]); UNPK(l1[6], l1[7], a1[3]);
            float s0 = 0.f, s1 = 0.f;
            #pragma unroll
            for (int j = 0; j < 8; j++) {
                l0[j] = exp2f(fmaf(l0[j], invS0, bjS[j])); s0 += l0[j];
                l1[j] = exp2f(fmaf(l1[j], invS1, bjS[j])); s1 += l1[j];
            }
            s0 += __shfl_xor_sync(0xffffffffu, s0, 1);
            s0 += __shfl_xor_sync(0xffffffffu, s0, 2);
            s0 += __shfl_xor_sync(0xffffffffu, s0, 4);
            s1 += __shfl_xor_sync(0xffffffffu, s1, 1);
            s1 += __shfl_xor_sync(0xffffffffu, s1, 2);
            s1 += __shfl_xor_sync(0xffffffffu, s1, 4);
            const float rs0 = __fdividef(1.f, s0);
            const float rs1 = __fdividef(1.f, s1);
            #pragma unroll
            for (int j = 0; j < 8; j++) {
                float p0 = l0[j] * rs0, p1 = l1[j] * rs1;
                asum_loc[j] += p0 + p1;
                l0[j] = p0 * inv0;            // fold per-position inv into weights
                l1[j] = p1 * inv1;
            }
            *(float4*)(SF + t0*64 + 4*g)      = make_float4(l0[0], l0[1], l0[2], l0[3]);
            *(float4*)(SF + t0*64 + 32 + 4*g) = make_float4(l0[4], l0[5], l0[6], l0[7]);
            *(float4*)(SF + t1*64 + 4*g)      = make_float4(l1[0], l1[1], l1[2], l1[3]);
            *(float4*)(SF + t1*64 + 32 + 4*g) = make_float4(l1[4], l1[5], l1[6], l1[7]);
        }
        __syncthreads();                       // SF ready

        // ---- Phase B: vlad += soft_hat @ x_raw^T (packed f32x2 along c) ----
        #pragma unroll 2
        for (int t = 0; t < TC; t++) {
            const float4 sv = *(const float4*)(SF + t*64 + kB);
            const unsigned rb = xtb + (unsigned)(t * (XT_STRIDE*4));
            const int swz = (t & 31) << 2;
            unsigned long long xp0, xp1, xp2, xp3;
            asm volatile("ld.shared.b64 %0,[%1];" : "=l"(xp0) : "r"(rb + (unsigned)((idxq[0] ^ swz) << 2)));
            asm volatile("ld.shared.b64 %0,[%1];" : "=l"(xp1) : "r"(rb + (unsigned)((idxq[1] ^ swz) << 2)));
            asm volatile("ld.shared.b64 %0,[%1];" : "=l"(xp2) : "r"(rb + (unsigned)((idxq[2] ^ swz) << 2)));
            asm volatile("ld.shared.b64 %0,[%1];" : "=l"(xp3) : "r"(rb + (unsigned)((idxq[3] ^ swz) << 2)));
            unsigned long long sp0, sp1, sp2, sp3;
            SPLAT(sp0, sv.x); SPLAT(sp1, sv.y); SPLAT(sp2, sv.z); SPLAT(sp3, sv.w);
            FMA2(accV[0][0], sp0, xp0); FMA2(accV[0][1], sp0, xp1);
            FMA2(accV[0][2], sp0, xp2); FMA2(accV[0][3], sp0, xp3);
            FMA2(accV[1][0], sp1, xp0); FMA2(accV[1][1], sp1, xp1);
            FMA2(accV[1][2], sp1, xp2); FMA2(accV[1][3], sp1, xp3);
            FMA2(accV[2][0], sp2, xp0); FMA2(accV[2][1], sp2, xp1);
            FMA2(accV[2][2], sp2, xp2); FMA2(accV[2][3], sp2, xp3);
            FMA2(accV[3][0], sp3, xp0); FMA2(accV[3][1], sp3, xp1);
            FMA2(accV[3][2], sp3, xp2); FMA2(accV[3][3], sp3, xp3);
        }
    }

    // ---- epilogue: vlad partials ----
    #pragma unroll
    for (int i = 0; i < 4; i++) {
        #pragma unroll
        for (int q = 0; q < 4; q++) {
            float lo, hi;
            UNPK(lo, hi, accV[i][q]);
            size_t base = ((size_t)n*KK + (kB + i))*CC + (32*q + 2*mm);
            atomicAdd(&g_vlad[base],     lo);
            atomicAdd(&g_vlad[base + 1], hi);
        }
    }
    // ---- a_sum reduction (stage in SF) ----
    __syncthreads();
    #pragma unroll
    for (int j = 0; j < 8; j++) SF[tid*8 + j] = asum_loc[j];
    __syncthreads();
    if (tid < 64) {
        int k = tid;
        int gg = (k < 32) ? (k >> 2) : ((k - 32) >> 2);
        int jj = (k < 32) ? (k & 3)  : (4 + (k & 3));
        float s = 0.f;
        for (int q = 0; q < 32; q++) s += SF[(q*8 + gg)*8 + jj];
        atomicAdd(&g_asum[n*KK + k], s);
    }
}

__global__ void zero_kernel()
{
    int i = blockIdx.x*256 + threadIdx.x;
    if (i < NN*KK*CC) g_vlad[i] = 0.f;
    if (i < NN*KK)    g_asum[i] = 0.f;
    if (i < NN)       g_gssq[i] = 0.f;
}

__global__ void finalize1(const float* __restrict__ centroids, float* __restrict__ out)
{
    __shared__ float red[4];
    const int n = blockIdx.y, k = blockIdx.x;
    const int c = threadIdx.x;   // 128 threads
    float a = g_asum[n*KK + k];
    float v = g_vlad[((size_t)n*KK + k)*CC + c] - a * centroids[k*CC + c];
    float ss = v*v;
    #pragma unroll
    for (int o = 16; o; o >>= 1) ss += __shfl_xor_sync(0xffffffffu, ss, o);
    if ((c & 31) == 0) red[c >> 5] = ss;
    __syncthreads();
    float tot = red[0] + red[1] + red[2] + red[3];
    float inv = 1.f / fmaxf(sqrtf(tot), 1e-12f);
    out[((size_t)n*KK + k)*CC + c] = v * inv;
    if (c == 0) atomicAdd(&g_gssq[n], tot * inv * inv);
}

__global__ void finalize2(float* __restrict__ out)
{
    int i = blockIdx.x*256 + threadIdx.x;   // 131072 total
    int n = i >> 13;
    out[i] *= 1.f / fmaxf(sqrtf(g_gssq[n]), 1e-12f);
}

extern "C" void kernel_launch(void* const* d_in, const int* in_sizes, int n_in,
                              void* d_out, int out_size)
{
    const float* x         = (const float*)d_in[0];
    const float* fc_w      = (const float*)d_in[1];
    const float* fc_b      = (const float*)d_in[2];
    const float* centroids = (const float*)d_in[3];
    float* out = (float*)d_out;

    cudaFuncSetAttribute((const void*)netvlad_main,
                         cudaFuncAttributeMaxDynamicSharedMemorySize,
                         SMEM_FLOATS * 4);

    zero_kernel<<<(NN*KK*CC + 255)/256, 256>>>();
    dim3 grid(SBLOCKS, NN);
    netvlad_main<<<grid, 256, SMEM_FLOATS * 4>>>(x, fc_w, fc_b);
    finalize1<<<dim3(KK, NN), 128>>>(centroids, out);
    finalize2<<<(NN*KK*CC + 255)/256, 256>>>(out);
}